// round 15
// baseline (speedup 1.0000x reference)
#include <cuda_runtime.h>
#include <cuda_bf16.h>
#include <cooperative_groups.h>
namespace cg = cooperative_groups;

#define SEQ   2048
#define INDIM 256
#define HID   256
#define G3    768
#define MTOT  (128 * SEQ)        // 262144 rows of x

// Precomputed input projection gx[b][t][768] (includes bx). ~805 MB scratch.
__device__ float g_gx[(size_t)MTOT * G3];
// bf16-pair decompositions (x = hi + lo exactly to ~2^-16 rel)
__device__ __nv_bfloat16 g_xhi[(size_t)MTOT * INDIM];
__device__ __nv_bfloat16 g_xlo[(size_t)MTOT * INDIM];
__device__ __nv_bfloat16 g_whi[G3 * INDIM];
__device__ __nv_bfloat16 g_wlo[G3 * INDIM];

// ---- helpers ----------------------------------------------------------------
static __device__ __forceinline__ unsigned long long dup2(float a) {
    unsigned long long r;
    asm("mov.b64 %0, {%1, %1};" : "=l"(r) : "f"(a));
    return r;
}
static __device__ __forceinline__ void fma2(unsigned long long& d,
                                            unsigned long long a,
                                            unsigned long long b) {
    asm("fma.rn.f32x2 %0, %1, %2, %0;" : "+l"(d) : "l"(a), "l"(b));
}
static __device__ __forceinline__ float2 unp2(unsigned long long v) {
    float2 r;
    asm("mov.b64 {%0, %1}, %2;" : "=f"(r.x), "=f"(r.y) : "l"(v));
    return r;
}
static __device__ __forceinline__ unsigned smem_u32(const void* p) {
    return (unsigned)__cvta_generic_to_shared(p);
}
static __device__ __forceinline__ void cp_async16(unsigned dst, const void* src) {
    asm volatile("cp.async.cg.shared.global [%0], [%1], 16;" :: "r"(dst), "l"(src));
}
static __device__ __forceinline__ void cp_commit() {
    asm volatile("cp.async.commit_group;" ::: "memory");
}
template <int N>
static __device__ __forceinline__ void cp_wait() {
    asm volatile("cp.async.wait_group %0;" :: "n"(N) : "memory");
}
static __device__ __forceinline__ void ldsm_x4(unsigned addr, unsigned& r0,
                                               unsigned& r1, unsigned& r2, unsigned& r3) {
    asm volatile("ldmatrix.sync.aligned.m8n8.x4.shared.b16 {%0,%1,%2,%3}, [%4];"
                 : "=r"(r0), "=r"(r1), "=r"(r2), "=r"(r3) : "r"(addr));
}
static __device__ __forceinline__ void mma16816(float* d, const unsigned* a,
                                                const unsigned* b) {
    asm volatile(
        "mma.sync.aligned.m16n8k16.row.col.f32.bf16.bf16.f32 "
        "{%0,%1,%2,%3}, {%4,%5,%6,%7}, {%8,%9}, {%0,%1,%2,%3};"
        : "+f"(d[0]), "+f"(d[1]), "+f"(d[2]), "+f"(d[3])
        : "r"(a[0]), "r"(a[1]), "r"(a[2]), "r"(a[3]), "r"(b[0]), "r"(b[1]));
}

// ---------------------------------------------------------------------------
// bf16-pair conversion: hi = bf16(v), lo = bf16(v - hi)
// ---------------------------------------------------------------------------
__global__ void cvt_pair(const float* __restrict__ src,
                         __nv_bfloat16* __restrict__ hi,
                         __nv_bfloat16* __restrict__ lo, int n4) {
    int i = blockIdx.x * blockDim.x + threadIdx.x;
    if (i >= n4) return;
    float4 v = ((const float4*)src)[i];
    __nv_bfloat16 h0 = __float2bfloat16(v.x);
    __nv_bfloat16 h1 = __float2bfloat16(v.y);
    __nv_bfloat16 h2 = __float2bfloat16(v.z);
    __nv_bfloat16 h3 = __float2bfloat16(v.w);
    __nv_bfloat162* hp = (__nv_bfloat162*)hi;
    __nv_bfloat162* lp = (__nv_bfloat162*)lo;
    hp[2 * i]     = __nv_bfloat162(h0, h1);
    hp[2 * i + 1] = __nv_bfloat162(h2, h3);
    lp[2 * i]     = __nv_bfloat162(__float2bfloat16(v.x - __bfloat162float(h0)),
                                   __float2bfloat16(v.y - __bfloat162float(h1)));
    lp[2 * i + 1] = __nv_bfloat162(__float2bfloat16(v.z - __bfloat162float(h2)),
                                   __float2bfloat16(v.w - __bfloat162float(h3)));
}

// ---------------------------------------------------------------------------
// Phase 1 v5: gx via mma.sync bf16-pair (3-term). K' = 3*256 = 768.
// BM=128, BN=128, BK=32 bf16, 8 warps (2m x 4n), warp tile 64x32.
// Tiles in smem with 80B-padded rows (conflict-free ldmatrix).
// ---------------------------------------------------------------------------
#define ARB 80
#define ATILE (128 * ARB)          // 10240 B
#define MMA_SMEM (4 * ATILE)       // A0,A1,B0,B1 = 40960 B

__global__ void __launch_bounds__(256, 2)
gx_mma(const float* __restrict__ bx) {
    extern __shared__ char smc[];
    char* At = smc;                 // [buf][row][80B]
    char* Bt = smc + 2 * ATILE;

    const int bid = blockIdx.x;
    const int mt = bid / 6;
    const int nt = bid % 6;
    const long m0 = (long)mt * 128;
    const int  n0 = nt * 128;
    const int tid = threadIdx.x;
    const int wid = tid >> 5;
    const int lane = tid & 31;
    const int warp_m = wid & 1;      // 0..1 (64 rows)
    const int warp_n = wid >> 1;     // 0..3 (32 cols)

    const unsigned sA = smem_u32(At);
    const unsigned sB = smem_u32(Bt);

    // chunk c in 0..23: segment s=c>>3 selects (A,B) pair; k0=(c&7)*32
    auto load_chunk = [&](int c) {
        const int buf = c & 1;
        const int seg = c >> 3;
        const int k0 = (c & 7) * 32;
        const __nv_bfloat16* Asrc = (seg == 2) ? g_xlo : g_xhi;
        const __nv_bfloat16* Bsrc = (seg == 1) ? g_wlo : g_whi;
#pragma unroll
        for (int e = tid * 2; e < tid * 2 + 2; e++) {
            int row = e >> 2;
            int ch = e & 3;
            cp_async16(sA + buf * ATILE + row * ARB + ch * 16,
                       Asrc + (m0 + row) * INDIM + k0 + ch * 8);
            cp_async16(sB + buf * ATILE + row * ARB + ch * 16,
                       Bsrc + (size_t)(n0 + row) * INDIM + k0 + ch * 8);
        }
        cp_commit();
    };

    load_chunk(0);
    load_chunk(1);

    float acc[4][4][4];
#pragma unroll
    for (int i = 0; i < 4; i++)
#pragma unroll
        for (int j = 0; j < 4; j++)
#pragma unroll
            for (int r = 0; r < 4; r++) acc[i][j][r] = 0.0f;

#pragma unroll 1
    for (int c = 0; c < 24; c++) {
        if (c < 22) cp_wait<1>(); else cp_wait<0>();
        __syncthreads();

        const unsigned aB = sA + (c & 1) * ATILE + warp_m * 64 * ARB;
        const unsigned bB = sB + (c & 1) * ATILE + warp_n * 32 * ARB;

#pragma unroll
        for (int kk = 0; kk < 2; kk++) {
            // B fragments: 2x ldmatrix.x4 -> bfr[ni][2]
            unsigned bfr[4][2];
#pragma unroll
            for (int h = 0; h < 2; h++) {
                int mtx = lane >> 3, r = lane & 7;
                int row = h * 16 + ((mtx >> 1) & 1) * 8 + r;
                int ch = kk * 2 + (mtx & 1);
                unsigned addr = bB + row * ARB + ch * 16;
                ldsm_x4(addr, bfr[2 * h][0], bfr[2 * h][1],
                        bfr[2 * h + 1][0], bfr[2 * h + 1][1]);
            }
            // A fragments + mma
#pragma unroll
            for (int mi = 0; mi < 4; mi++) {
                unsigned afr[4];
                {
                    int mtx = lane >> 3, r = lane & 7;
                    int row = mi * 16 + (mtx & 1) * 8 + r;
                    int ch = kk * 2 + (mtx >> 1);
                    unsigned addr = aB + row * ARB + ch * 16;
                    ldsm_x4(addr, afr[0], afr[1], afr[2], afr[3]);
                }
#pragma unroll
                for (int ni = 0; ni < 4; ni++)
                    mma16816(acc[mi][ni], afr, bfr[ni]);
            }
        }
        __syncthreads();
        if (c + 2 < 24) load_chunk(c + 2);
    }

    // epilogue: bias + store. c0,c1 -> row gid, cols 2t,2t+1; c2,c3 -> row gid+8
    const int gid = lane >> 2;
    const int tq = lane & 3;
#pragma unroll
    for (int ni = 0; ni < 4; ni++) {
        int n_g = n0 + warp_n * 32 + ni * 8 + tq * 2;
        float b0 = bx[n_g], b1 = bx[n_g + 1];
#pragma unroll
        for (int mi = 0; mi < 4; mi++) {
            long m_g = m0 + warp_m * 64 + mi * 16 + gid;
            float* p0 = &g_gx[m_g * G3 + n_g];
            float* p1 = &g_gx[(m_g + 8) * G3 + n_g];
            *(float2*)p0 = make_float2(acc[mi][ni][0] + b0, acc[mi][ni][1] + b1);
            *(float2*)p1 = make_float2(acc[mi][ni][2] + b0, acc[mi][ni][3] + b1);
        }
    }
}

// ---------------------------------------------------------------------------
// Phase 2: persistent recurrence v9 (EXACT round-10 best: 6017 us).
// ---------------------------------------------------------------------------
#define CLUSTER 4
#define UB    64
#define ROWS  192
#define NTHR  384
#define HPAD  256
#define PBLK  772

#define OFF_HB (ROWS * 256)
#define OFF_P  (OFF_HB + 2 * 4 * HPAD)
#define REC_SMEM ((OFF_P + 8 * PBLK) * 4)   // 229504 B

__global__ void __launch_bounds__(NTHR, 1) __cluster_dims__(CLUSTER, 1, 1)
gru_rec(const float* __restrict__ Wh, const float* __restrict__ bh,
        const float* __restrict__ Wfc, const float* __restrict__ bfc,
        float* __restrict__ out) {
    extern __shared__ float sm[];
    float* ws   = sm;
    float* hbuf = sm + OFF_HB;
    float* part = sm + OFF_P;

    cg::cluster_group cl = cg::this_cluster();
    const int rank = (int)cl.block_rank();
    const int clid = (int)blockIdx.x / CLUSTER;
    const int tid  = threadIdx.x;
    const int U0   = rank * UB;
    const int B0   = clid * 4;

    for (int e4 = tid; e4 < ROWS * (HID / 4); e4 += NTHR) {
        int r = e4 >> 6;
        int k = (e4 & 63) << 2;
        int grow = (r >> 6) * HID + U0 + (r & 63);
        *(float4*)&ws[r * 256 + k] = *(const float4*)&Wh[(long)grow * HID + k];
    }
    for (int i = tid; i < 2 * 4 * HPAD; i += NTHR)
        hbuf[i] = 0.0f;
    __syncthreads();

    const int g = tid >> 3;
    const int q = tid & 7;
    const float* wp = ws + (g << 2) * 256;

    unsigned long long wa0[16], wa1[16];
#pragma unroll
    for (int s = 0; s < 8; s++) {
        const int kb = (s * 8 + q) * 4;
        ulonglong2 t0 = *(const ulonglong2*)(wp + 0 * 256 + kb);
        ulonglong2 t1 = *(const ulonglong2*)(wp + 1 * 256 + kb);
        wa0[2 * s] = t0.x; wa0[2 * s + 1] = t0.y;
        wa1[2 * s] = t1.x; wa1[2 * s + 1] = t1.y;
    }

    const int gu = tid & 63;
    const int gb = (tid >> 6) & 3;
    const bool is_gate = (tid < 256);
    const float bhr = is_gate ? bh[U0 + gu]       : 0.f;
    const float bhz = is_gate ? bh[256 + U0 + gu] : 0.f;
    const float bhn = is_gate ? bh[512 + U0 + gu] : 0.f;
    float hprev = 0.0f;

    float* peer_hb[CLUSTER];
#pragma unroll
    for (int rr = 0; rr < CLUSTER; rr++)
        peer_hb[rr] = (float*)cl.map_shared_rank(hbuf, rr);

    const float* gxp = g_gx + ((long)(B0 + gb) * SEQ) * G3 + (U0 + gu);

    cl.sync();

    for (int t = 0; t < SEQ; t++) {
        const int cur = t & 1;
        const int nxt = cur ^ 1;

        float gcr = 0.f, gcz = 0.f, gcn = 0.f;
        if (is_gate) {
            const float* gp = gxp + (long)t * G3;
            gcr = gp[0]; gcz = gp[256]; gcn = gp[512];
        }

        const float* hb = hbuf + cur * 4 * HPAD;
        unsigned long long acc[16];
#pragma unroll
        for (int i = 0; i < 16; i++) acc[i] = 0ull;

#pragma unroll
        for (int s = 0; s < 8; s++) {
            const int kb = (s * 8 + q) * 4;
            const unsigned long long w0x = wa0[2 * s], w0y = wa0[2 * s + 1];
            const unsigned long long w1x = wa1[2 * s], w1y = wa1[2 * s + 1];
            ulonglong2 w2 = *(const ulonglong2*)(wp + 2 * 256 + kb);
            ulonglong2 w3 = *(const ulonglong2*)(wp + 3 * 256 + kb);
            ulonglong2 h0 = *(const ulonglong2*)(hb + 0 * HPAD + kb);
            ulonglong2 h1 = *(const ulonglong2*)(hb + 1 * HPAD + kb);
            ulonglong2 h2 = *(const ulonglong2*)(hb + 2 * HPAD + kb);
            ulonglong2 h3 = *(const ulonglong2*)(hb + 3 * HPAD + kb);
            fma2(acc[0],  w0x, h0.x); fma2(acc[0],  w0y, h0.y);
            fma2(acc[1],  w1x, h0.x); fma2(acc[1],  w1y, h0.y);
            fma2(acc[2],  w2.x, h0.x); fma2(acc[2],  w2.y, h0.y);
            fma2(acc[3],  w3.x, h0.x); fma2(acc[3],  w3.y, h0.y);
            fma2(acc[4],  w0x, h1.x); fma2(acc[4],  w0y, h1.y);
            fma2(acc[5],  w1x, h1.x); fma2(acc[5],  w1y, h1.y);
            fma2(acc[6],  w2.x, h1.x); fma2(acc[6],  w2.y, h1.y);
            fma2(acc[7],  w3.x, h1.x); fma2(acc[7],  w3.y, h1.y);
            fma2(acc[8],  w0x, h2.x); fma2(acc[8],  w0y, h2.y);
            fma2(acc[9],  w1x, h2.x); fma2(acc[9],  w1y, h2.y);
            fma2(acc[10], w2.x, h2.x); fma2(acc[10], w2.y, h2.y);
            fma2(acc[11], w3.x, h2.x); fma2(acc[11], w3.y, h2.y);
            fma2(acc[12], w0x, h3.x); fma2(acc[12], w0y, h3.y);
            fma2(acc[13], w1x, h3.x); fma2(acc[13], w1y, h3.y);
            fma2(acc[14], w2.x, h3.x); fma2(acc[14], w2.y, h3.y);
            fma2(acc[15], w3.x, h3.x); fma2(acc[15], w3.y, h3.y);
        }

        {
            float* pq = part + q * PBLK + (g << 2);
#pragma unroll
            for (int b = 0; b < 4; b++) {
                float2 f0 = unp2(acc[b * 4 + 0]);
                float2 f1 = unp2(acc[b * 4 + 1]);
                float2 f2 = unp2(acc[b * 4 + 2]);
                float2 f3 = unp2(acc[b * 4 + 3]);
                float4 o;
                o.x = f0.x + f0.y; o.y = f1.x + f1.y;
                o.z = f2.x + f2.y; o.w = f3.x + f3.y;
                *(float4*)(pq + b * 192) = o;
            }
        }
        __syncthreads();

        if (is_gate) {
            float sr = bhr, sz = bhz, sn = bhn;
#pragma unroll
            for (int qq = 0; qq < 8; qq++) {
                const float* pq = part + qq * PBLK + gb * 192;
                sr += pq[gu];
                sz += pq[64 + gu];
                sn += pq[128 + gu];
            }
            float rg = __fdividef(1.0f, 1.0f + __expf(-(gcr + sr)));
            float zg = __fdividef(1.0f, 1.0f + __expf(-(gcz + sz)));
            float na = gcn + rg * sn;
            float ng = 2.0f * __fdividef(1.0f, 1.0f + __expf(-2.0f * na)) - 1.0f;
            float hnew = ng + zg * (hprev - ng);
            hprev = hnew;
            const int off = (nxt * 4 + gb) * HPAD + (U0 + gu);
#pragma unroll
            for (int rr = 0; rr < CLUSTER; rr++)
                peer_hb[rr][off] = hnew;
        }
        cl.sync();
    }

    if (rank == 0) {
        const int w = tid >> 5, lane = tid & 31;
        if (w < 8) {
            const int bb = w >> 1, o = w & 1;
            const float* hf = hbuf + bb * HPAD;
            float s = 0.f;
            for (int k = lane; k < HID; k += 32)
                s += hf[k] * __ldg(&Wfc[o * HID + k]);
#pragma unroll
            for (int d = 16; d > 0; d >>= 1)
                s += __shfl_xor_sync(0xFFFFFFFFu, s, d);
            if (lane == 0)
                out[(B0 + bb) * 2 + o] = s + bfc[o];
        }
    }
}

// ---------------------------------------------------------------------------
extern "C" void kernel_launch(void* const* d_in, const int* in_sizes, int n_in,
                              void* d_out, int out_size) {
    const float* x   = (const float*)d_in[0];
    const float* Wx  = (const float*)d_in[1];
    const float* bx  = (const float*)d_in[2];
    const float* Wh  = (const float*)d_in[3];
    const float* bh  = (const float*)d_in[4];
    const float* Wfc = (const float*)d_in[5];
    const float* bfc = (const float*)d_in[6];
    float* out = (float*)d_out;

    cudaFuncSetAttribute(gx_mma, cudaFuncAttributeMaxDynamicSharedMemorySize, MMA_SMEM);
    cudaFuncSetAttribute(gru_rec, cudaFuncAttributeMaxDynamicSharedMemorySize, REC_SMEM);

    // resolve device scratch addresses
    __nv_bfloat16 *xhi, *xlo, *whi, *wlo;
    cudaGetSymbolAddress((void**)&xhi, g_xhi);
    cudaGetSymbolAddress((void**)&xlo, g_xlo);
    cudaGetSymbolAddress((void**)&whi, g_whi);
    cudaGetSymbolAddress((void**)&wlo, g_wlo);

    const int nx4 = MTOT * INDIM / 4;       // 16,777,216
    const int nw4 = G3 * INDIM / 4;         // 49,152
    cvt_pair<<<(nx4 + 255) / 256, 256>>>(x, xhi, xlo, nx4);
    cvt_pair<<<(nw4 + 255) / 256, 256>>>(Wx, whi, wlo, nw4);

    gx_mma<<<(MTOT / 128) * (G3 / 128), 256, MMA_SMEM>>>(bx);
    gru_rec<<<32 * CLUSTER, NTHR, REC_SMEM>>>(Wh, bh, Wfc, bfc, out);
}

// round 16
// speedup vs baseline: 1.3737x; 1.3737x over previous
#include <cuda_runtime.h>
#include <cooperative_groups.h>
namespace cg = cooperative_groups;

#define SEQ   2048
#define INDIM 256
#define HID   256
#define G3    768

// Precomputed input projection gx[b][t][768] (includes bx). ~805 MB scratch.
__device__ float g_gx[(size_t)128 * SEQ * G3];

// ---- f32x2 packed helpers (SASS FFMA2 path, PTX-only) ----------------------
static __device__ __forceinline__ unsigned long long dup2(float a) {
    unsigned long long r;
    asm("mov.b64 %0, {%1, %1};" : "=l"(r) : "f"(a));
    return r;
}
static __device__ __forceinline__ void fma2(unsigned long long& d,
                                            unsigned long long a,
                                            unsigned long long b) {
    asm("fma.rn.f32x2 %0, %1, %2, %0;" : "+l"(d) : "l"(a), "l"(b));
}
static __device__ __forceinline__ float2 unp2(unsigned long long v) {
    float2 r;
    asm("mov.b64 {%0, %1}, %2;" : "=f"(r.x), "=f"(r.y) : "l"(v));
    return r;
}
static __device__ __forceinline__ unsigned smem_u32(const void* p) {
    return (unsigned)__cvta_generic_to_shared(p);
}
static __device__ __forceinline__ void cp_async4(unsigned dst, const void* src) {
    asm volatile("cp.async.ca.shared.global [%0], [%1], 4;" :: "r"(dst), "l"(src));
}
static __device__ __forceinline__ void cp_commit() {
    asm volatile("cp.async.commit_group;" ::: "memory");
}
template <int N>
static __device__ __forceinline__ void cp_wait() {
    asm volatile("cp.async.wait_group %0;" :: "n"(N) : "memory");
}

// ---------------------------------------------------------------------------
// Phase 1 v6: gx = x @ Wx^T + bx.
// BM=128, BN=128, BK=32, 256 threads, 8x8 microtile, double-buffered cp.async.
// FIX vs v2: per-thread m-strip split 8 -> 4+4 (tm = (tid&15)*4 and tm+64):
// A-fragment LDS.128 lanes now stride 16B -> all 32 banks distinct ->
// conflict-free (v2's 32B stride was 2-way conflicted, making gx LSU-bound).
// ---------------------------------------------------------------------------
#define GXP 132
#define GX_BUF (32 * GXP)
#define GX_SMEM (4 * GX_BUF * 4)      // 67584 B

__global__ void __launch_bounds__(256, 2)
gx_gemm(const float* __restrict__ x, const float* __restrict__ Wx,
        const float* __restrict__ bx) {
    extern __shared__ float sm[];
    float* As = sm;
    float* Bs = sm + 2 * GX_BUF;

    const int bid = blockIdx.x;
    const int mt = bid / 6;
    const int nt = bid % 6;
    const long m0 = (long)mt * 128;
    const int  n0 = nt * 128;
    const int tid = threadIdx.x;
    const int wid = tid >> 5;
    const int lane = tid & 31;

    const unsigned sA = smem_u32(As);
    const unsigned sB = smem_u32(Bs);

    auto load_chunk = [&](int c) {
        const int buf = c & 1;
        const int k0 = c * 32;
        const unsigned dA = sA + (buf * GX_BUF + lane * GXP) * 4;
        const unsigned dB = sB + (buf * GX_BUF + lane * GXP) * 4;
        const float* gA = x + (m0 + wid * 16) * INDIM + k0 + lane;
        const float* gB = Wx + (long)(n0 + wid * 16) * INDIM + k0 + lane;
#pragma unroll
        for (int i = 0; i < 16; i++) {
            int row = wid * 16 + i;
            cp_async4(dA + row * 4, gA + i * INDIM);
            cp_async4(dB + row * 4, gB + i * INDIM);
        }
        cp_commit();
    };

    load_chunk(0);
    load_chunk(1);

    const int tm = (tid & 15) * 4;        // strip 1: rows tm..tm+3
    const int tn = (tid >> 4) * 8;        // strip 2: rows tm+64..tm+67

    unsigned long long acc[4][8];
#pragma unroll
    for (int i = 0; i < 4; i++)
#pragma unroll
        for (int j = 0; j < 8; j++) acc[i][j] = 0ull;

#pragma unroll 1
    for (int c = 0; c < 8; c++) {
        if (c < 6) cp_wait<1>(); else cp_wait<0>();
        __syncthreads();

        const float* ab = As + (c & 1) * GX_BUF;
        const float* bb = Bs + (c & 1) * GX_BUF;
#pragma unroll 8
        for (int k = 0; k < 32; k++) {
            // conflict-free: lanes 0..15 read 16B chunks at 16B stride
            ulonglong2 a0 = *(const ulonglong2*)(ab + k * GXP + tm);
            ulonglong2 a1 = *(const ulonglong2*)(ab + k * GXP + tm + 64);
            float4 b0 = *(const float4*)(bb + k * GXP + tn);
            float4 b1 = *(const float4*)(bb + k * GXP + tn + 4);
            unsigned long long am[4] = {a0.x, a0.y, a1.x, a1.y};
            float bn[8] = {b0.x, b0.y, b0.z, b0.w, b1.x, b1.y, b1.z, b1.w};
#pragma unroll
            for (int j = 0; j < 8; j++) {
                unsigned long long bd = dup2(bn[j]);
#pragma unroll
                for (int i = 0; i < 4; i++)
                    fma2(acc[i][j], am[i], bd);
            }
        }
        __syncthreads();
        if (c + 2 < 8) load_chunk(c + 2);
    }

    // epilogue: acc[i] row pairs: i=0 ->(tm,tm+1), 1 ->(tm+2,tm+3),
    //                             2 ->(tm+64,tm+65), 3 ->(tm+66,tm+67)
    float bn[8];
#pragma unroll
    for (int j = 0; j < 8; j++) bn[j] = bx[n0 + tn + j];
#pragma unroll
    for (int i = 0; i < 4; i++) {
        const int mrow = (i < 2) ? (tm + 2 * i) : (tm + 64 + 2 * (i - 2));
        float lo[8], hi[8];
#pragma unroll
        for (int j = 0; j < 8; j++) {
            float2 f = unp2(acc[i][j]);
            lo[j] = f.x + bn[j];
            hi[j] = f.y + bn[j];
        }
        float* r0 = &g_gx[(m0 + mrow) * G3 + n0 + tn];
        float* r1 = r0 + G3;
        *(float4*)(r0)     = make_float4(lo[0], lo[1], lo[2], lo[3]);
        *(float4*)(r0 + 4) = make_float4(lo[4], lo[5], lo[6], lo[7]);
        *(float4*)(r1)     = make_float4(hi[0], hi[1], hi[2], hi[3]);
        *(float4*)(r1 + 4) = make_float4(hi[4], hi[5], hi[6], hi[7]);
    }
}

// ---------------------------------------------------------------------------
// Phase 2: persistent recurrence v9 (EXACT round-10 best: 6017 us).
// cluster.sync is the proven-optimal step barrier.
// ---------------------------------------------------------------------------
#define CLUSTER 4
#define UB    64
#define ROWS  192
#define NTHR  384
#define HPAD  256
#define PBLK  772

#define OFF_HB (ROWS * 256)
#define OFF_P  (OFF_HB + 2 * 4 * HPAD)
#define REC_SMEM ((OFF_P + 8 * PBLK) * 4)   // 229504 B

__global__ void __launch_bounds__(NTHR, 1) __cluster_dims__(CLUSTER, 1, 1)
gru_rec(const float* __restrict__ Wh, const float* __restrict__ bh,
        const float* __restrict__ Wfc, const float* __restrict__ bfc,
        float* __restrict__ out) {
    extern __shared__ float sm[];
    float* ws   = sm;
    float* hbuf = sm + OFF_HB;
    float* part = sm + OFF_P;

    cg::cluster_group cl = cg::this_cluster();
    const int rank = (int)cl.block_rank();
    const int clid = (int)blockIdx.x / CLUSTER;
    const int tid  = threadIdx.x;
    const int U0   = rank * UB;
    const int B0   = clid * 4;

    for (int e4 = tid; e4 < ROWS * (HID / 4); e4 += NTHR) {
        int r = e4 >> 6;
        int k = (e4 & 63) << 2;
        int grow = (r >> 6) * HID + U0 + (r & 63);
        *(float4*)&ws[r * 256 + k] = *(const float4*)&Wh[(long)grow * HID + k];
    }
    for (int i = tid; i < 2 * 4 * HPAD; i += NTHR)
        hbuf[i] = 0.0f;
    __syncthreads();

    const int g = tid >> 3;
    const int q = tid & 7;
    const float* wp = ws + (g << 2) * 256;

    unsigned long long wa0[16], wa1[16];
#pragma unroll
    for (int s = 0; s < 8; s++) {
        const int kb = (s * 8 + q) * 4;
        ulonglong2 t0 = *(const ulonglong2*)(wp + 0 * 256 + kb);
        ulonglong2 t1 = *(const ulonglong2*)(wp + 1 * 256 + kb);
        wa0[2 * s] = t0.x; wa0[2 * s + 1] = t0.y;
        wa1[2 * s] = t1.x; wa1[2 * s + 1] = t1.y;
    }

    const int gu = tid & 63;
    const int gb = (tid >> 6) & 3;
    const bool is_gate = (tid < 256);
    const float bhr = is_gate ? bh[U0 + gu]       : 0.f;
    const float bhz = is_gate ? bh[256 + U0 + gu] : 0.f;
    const float bhn = is_gate ? bh[512 + U0 + gu] : 0.f;
    float hprev = 0.0f;

    float* peer_hb[CLUSTER];
#pragma unroll
    for (int rr = 0; rr < CLUSTER; rr++)
        peer_hb[rr] = (float*)cl.map_shared_rank(hbuf, rr);

    const float* gxp = g_gx + ((long)(B0 + gb) * SEQ) * G3 + (U0 + gu);

    cl.sync();

    for (int t = 0; t < SEQ; t++) {
        const int cur = t & 1;
        const int nxt = cur ^ 1;

        float gcr = 0.f, gcz = 0.f, gcn = 0.f;
        if (is_gate) {
            const float* gp = gxp + (long)t * G3;
            gcr = gp[0]; gcz = gp[256]; gcn = gp[512];
        }

        const float* hb = hbuf + cur * 4 * HPAD;
        unsigned long long acc[16];
#pragma unroll
        for (int i = 0; i < 16; i++) acc[i] = 0ull;

#pragma unroll
        for (int s = 0; s < 8; s++) {
            const int kb = (s * 8 + q) * 4;
            const unsigned long long w0x = wa0[2 * s], w0y = wa0[2 * s + 1];
            const unsigned long long w1x = wa1[2 * s], w1y = wa1[2 * s + 1];
            ulonglong2 w2 = *(const ulonglong2*)(wp + 2 * 256 + kb);
            ulonglong2 w3 = *(const ulonglong2*)(wp + 3 * 256 + kb);
            ulonglong2 h0 = *(const ulonglong2*)(hb + 0 * HPAD + kb);
            ulonglong2 h1 = *(const ulonglong2*)(hb + 1 * HPAD + kb);
            ulonglong2 h2 = *(const ulonglong2*)(hb + 2 * HPAD + kb);
            ulonglong2 h3 = *(const ulonglong2*)(hb + 3 * HPAD + kb);
            fma2(acc[0],  w0x, h0.x); fma2(acc[0],  w0y, h0.y);
            fma2(acc[1],  w1x, h0.x); fma2(acc[1],  w1y, h0.y);
            fma2(acc[2],  w2.x, h0.x); fma2(acc[2],  w2.y, h0.y);
            fma2(acc[3],  w3.x, h0.x); fma2(acc[3],  w3.y, h0.y);
            fma2(acc[4],  w0x, h1.x); fma2(acc[4],  w0y, h1.y);
            fma2(acc[5],  w1x, h1.x); fma2(acc[5],  w1y, h1.y);
            fma2(acc[6],  w2.x, h1.x); fma2(acc[6],  w2.y, h1.y);
            fma2(acc[7],  w3.x, h1.x); fma2(acc[7],  w3.y, h1.y);
            fma2(acc[8],  w0x, h2.x); fma2(acc[8],  w0y, h2.y);
            fma2(acc[9],  w1x, h2.x); fma2(acc[9],  w1y, h2.y);
            fma2(acc[10], w2.x, h2.x); fma2(acc[10], w2.y, h2.y);
            fma2(acc[11], w3.x, h2.x); fma2(acc[11], w3.y, h2.y);
            fma2(acc[12], w0x, h3.x); fma2(acc[12], w0y, h3.y);
            fma2(acc[13], w1x, h3.x); fma2(acc[13], w1y, h3.y);
            fma2(acc[14], w2.x, h3.x); fma2(acc[14], w2.y, h3.y);
            fma2(acc[15], w3.x, h3.x); fma2(acc[15], w3.y, h3.y);
        }

        {
            float* pq = part + q * PBLK + (g << 2);
#pragma unroll
            for (int b = 0; b < 4; b++) {
                float2 f0 = unp2(acc[b * 4 + 0]);
                float2 f1 = unp2(acc[b * 4 + 1]);
                float2 f2 = unp2(acc[b * 4 + 2]);
                float2 f3 = unp2(acc[b * 4 + 3]);
                float4 o;
                o.x = f0.x + f0.y; o.y = f1.x + f1.y;
                o.z = f2.x + f2.y; o.w = f3.x + f3.y;
                *(float4*)(pq + b * 192) = o;
            }
        }
        __syncthreads();

        if (is_gate) {
            float sr = bhr, sz = bhz, sn = bhn;
#pragma unroll
            for (int qq = 0; qq < 8; qq++) {
                const float* pq = part + qq * PBLK + gb * 192;
                sr += pq[gu];
                sz += pq[64 + gu];
                sn += pq[128 + gu];
            }
            float rg = __fdividef(1.0f, 1.0f + __expf(-(gcr + sr)));
            float zg = __fdividef(1.0f, 1.0f + __expf(-(gcz + sz)));
            float na = gcn + rg * sn;
            float ng = 2.0f * __fdividef(1.0f, 1.0f + __expf(-2.0f * na)) - 1.0f;
            float hnew = ng + zg * (hprev - ng);
            hprev = hnew;
            const int off = (nxt * 4 + gb) * HPAD + (U0 + gu);
#pragma unroll
            for (int rr = 0; rr < CLUSTER; rr++)
                peer_hb[rr][off] = hnew;
        }
        cl.sync();
    }

    if (rank == 0) {
        const int w = tid >> 5, lane = tid & 31;
        if (w < 8) {
            const int bb = w >> 1, o = w & 1;
            const float* hf = hbuf + bb * HPAD;
            float s = 0.f;
            for (int k = lane; k < HID; k += 32)
                s += hf[k] * __ldg(&Wfc[o * HID + k]);
#pragma unroll
            for (int d = 16; d > 0; d >>= 1)
                s += __shfl_xor_sync(0xFFFFFFFFu, s, d);
            if (lane == 0)
                out[(B0 + bb) * 2 + o] = s + bfc[o];
        }
    }
}

// ---------------------------------------------------------------------------
extern "C" void kernel_launch(void* const* d_in, const int* in_sizes, int n_in,
                              void* d_out, int out_size) {
    const float* x   = (const float*)d_in[0];
    const float* Wx  = (const float*)d_in[1];
    const float* bx  = (const float*)d_in[2];
    const float* Wh  = (const float*)d_in[3];
    const float* bh  = (const float*)d_in[4];
    const float* Wfc = (const float*)d_in[5];
    const float* bfc = (const float*)d_in[6];
    float* out = (float*)d_out;

    cudaFuncSetAttribute(gx_gemm, cudaFuncAttributeMaxDynamicSharedMemorySize, GX_SMEM);
    cudaFuncSetAttribute(gru_rec, cudaFuncAttributeMaxDynamicSharedMemorySize, REC_SMEM);

    const int mtiles = (128 * SEQ) / 128;    // 2048
    const int ntiles = G3 / 128;             // 6
    gx_gemm<<<mtiles * ntiles, 256, GX_SMEM>>>(x, Wx, bx);
    gru_rec<<<32 * CLUSTER, NTHR, REC_SMEM>>>(Wh, bh, Wfc, bfc, out);
}

// round 17
// speedup vs baseline: 1.3904x; 1.0122x over previous
#include <cuda_runtime.h>
#include <cooperative_groups.h>
namespace cg = cooperative_groups;

#define SEQ   2048
#define INDIM 256
#define HID   256
#define G3    768

// Precomputed input projection gx[b][t][768] (includes bx). ~805 MB scratch.
__device__ float g_gx[(size_t)128 * SEQ * G3];

// ---- f32x2 packed helpers (SASS FFMA2 path, PTX-only) ----------------------
static __device__ __forceinline__ unsigned long long dup2(float a) {
    unsigned long long r;
    asm("mov.b64 %0, {%1, %1};" : "=l"(r) : "f"(a));
    return r;
}
static __device__ __forceinline__ void fma2(unsigned long long& d,
                                            unsigned long long a,
                                            unsigned long long b) {
    asm("fma.rn.f32x2 %0, %1, %2, %0;" : "+l"(d) : "l"(a), "l"(b));
}
static __device__ __forceinline__ float2 unp2(unsigned long long v) {
    float2 r;
    asm("mov.b64 {%0, %1}, %2;" : "=f"(r.x), "=f"(r.y) : "l"(v));
    return r;
}
static __device__ __forceinline__ unsigned smem_u32(const void* p) {
    return (unsigned)__cvta_generic_to_shared(p);
}
static __device__ __forceinline__ void cp_async4(unsigned dst, const void* src) {
    asm volatile("cp.async.ca.shared.global [%0], [%1], 4;" :: "r"(dst), "l"(src));
}
static __device__ __forceinline__ void cp_commit() {
    asm volatile("cp.async.commit_group;" ::: "memory");
}
template <int N>
static __device__ __forceinline__ void cp_wait() {
    asm volatile("cp.async.wait_group %0;" :: "n"(N) : "memory");
}
static __device__ __forceinline__ void cluster_arrive() {
    asm volatile("barrier.cluster.arrive.aligned;" ::: "memory");
}
static __device__ __forceinline__ void cluster_wait() {
    asm volatile("barrier.cluster.wait.aligned;" ::: "memory");
}

// ---------------------------------------------------------------------------
// Phase 1 v6: gx = x @ Wx^T + bx.  (unchanged from round 15 — best known)
// ---------------------------------------------------------------------------
#define GXP 132
#define GX_BUF (32 * GXP)
#define GX_SMEM (4 * GX_BUF * 4)      // 67584 B

__global__ void __launch_bounds__(256, 2)
gx_gemm(const float* __restrict__ x, const float* __restrict__ Wx,
        const float* __restrict__ bx) {
    extern __shared__ float sm[];
    float* As = sm;
    float* Bs = sm + 2 * GX_BUF;

    const int bid = blockIdx.x;
    const int mt = bid / 6;
    const int nt = bid % 6;
    const long m0 = (long)mt * 128;
    const int  n0 = nt * 128;
    const int tid = threadIdx.x;
    const int wid = tid >> 5;
    const int lane = tid & 31;

    const unsigned sA = smem_u32(As);
    const unsigned sB = smem_u32(Bs);

    auto load_chunk = [&](int c) {
        const int buf = c & 1;
        const int k0 = c * 32;
        const unsigned dA = sA + (buf * GX_BUF + lane * GXP) * 4;
        const unsigned dB = sB + (buf * GX_BUF + lane * GXP) * 4;
        const float* gA = x + (m0 + wid * 16) * INDIM + k0 + lane;
        const float* gB = Wx + (long)(n0 + wid * 16) * INDIM + k0 + lane;
#pragma unroll
        for (int i = 0; i < 16; i++) {
            int row = wid * 16 + i;
            cp_async4(dA + row * 4, gA + i * INDIM);
            cp_async4(dB + row * 4, gB + i * INDIM);
        }
        cp_commit();
    };

    load_chunk(0);
    load_chunk(1);

    const int tm = (tid & 15) * 4;
    const int tn = (tid >> 4) * 8;

    unsigned long long acc[4][8];
#pragma unroll
    for (int i = 0; i < 4; i++)
#pragma unroll
        for (int j = 0; j < 8; j++) acc[i][j] = 0ull;

#pragma unroll 1
    for (int c = 0; c < 8; c++) {
        if (c < 6) cp_wait<1>(); else cp_wait<0>();
        __syncthreads();

        const float* ab = As + (c & 1) * GX_BUF;
        const float* bb = Bs + (c & 1) * GX_BUF;
#pragma unroll 8
        for (int k = 0; k < 32; k++) {
            ulonglong2 a0 = *(const ulonglong2*)(ab + k * GXP + tm);
            ulonglong2 a1 = *(const ulonglong2*)(ab + k * GXP + tm + 64);
            float4 b0 = *(const float4*)(bb + k * GXP + tn);
            float4 b1 = *(const float4*)(bb + k * GXP + tn + 4);
            unsigned long long am[4] = {a0.x, a0.y, a1.x, a1.y};
            float bn[8] = {b0.x, b0.y, b0.z, b0.w, b1.x, b1.y, b1.z, b1.w};
#pragma unroll
            for (int j = 0; j < 8; j++) {
                unsigned long long bd = dup2(bn[j]);
#pragma unroll
                for (int i = 0; i < 4; i++)
                    fma2(acc[i][j], am[i], bd);
            }
        }
        __syncthreads();
        if (c + 2 < 8) load_chunk(c + 2);
    }

    float bn[8];
#pragma unroll
    for (int j = 0; j < 8; j++) bn[j] = bx[n0 + tn + j];
#pragma unroll
    for (int i = 0; i < 4; i++) {
        const int mrow = (i < 2) ? (tm + 2 * i) : (tm + 64 + 2 * (i - 2));
        float lo[8], hi[8];
#pragma unroll
        for (int j = 0; j < 8; j++) {
            float2 f = unp2(acc[i][j]);
            lo[j] = f.x + bn[j];
            hi[j] = f.y + bn[j];
        }
        float* r0 = &g_gx[(m0 + mrow) * G3 + n0 + tn];
        float* r1 = r0 + G3;
        *(float4*)(r0)     = make_float4(lo[0], lo[1], lo[2], lo[3]);
        *(float4*)(r0 + 4) = make_float4(lo[4], lo[5], lo[6], lo[7]);
        *(float4*)(r1)     = make_float4(hi[0], hi[1], hi[2], hi[3]);
        *(float4*)(r1 + 4) = make_float4(hi[4], hi[5], hi[6], hi[7]);
    }
}

// ---------------------------------------------------------------------------
// Phase 2: persistent recurrence v11 — own-k pre-dot overlaps cluster barrier.
// Per step: pre-dot over this CTA's own 64-k slice (s = S0, S0+1; the h values
// its own gate wrote locally) BEFORE cluster_wait; remaining 6 slabs after.
// Rank-templated so weight-register indices stay compile-time.
// ---------------------------------------------------------------------------
#define CLUSTER 4
#define UB    64
#define ROWS  192
#define NTHR  384
#define HPAD  256
#define PBLK  772

#define OFF_HB (ROWS * 256)
#define OFF_P  (OFF_HB + 2 * 4 * HPAD)
#define REC_SMEM ((OFF_P + 8 * PBLK) * 4)   // 229504 B

#define DOT_S(s) { \
    const int kb = ((s) * 8 + q) * 4; \
    const unsigned long long w0x = wa0[2 * (s)], w0y = wa0[2 * (s) + 1]; \
    const unsigned long long w1x = wa1[2 * (s)], w1y = wa1[2 * (s) + 1]; \
    ulonglong2 w2 = *(const ulonglong2*)(wp + 2 * 256 + kb); \
    ulonglong2 w3 = *(const ulonglong2*)(wp + 3 * 256 + kb); \
    ulonglong2 h0 = *(const ulonglong2*)(hb + 0 * HPAD + kb); \
    ulonglong2 h1 = *(const ulonglong2*)(hb + 1 * HPAD + kb); \
    ulonglong2 h2 = *(const ulonglong2*)(hb + 2 * HPAD + kb); \
    ulonglong2 h3 = *(const ulonglong2*)(hb + 3 * HPAD + kb); \
    fma2(acc[0],  w0x, h0.x); fma2(acc[0],  w0y, h0.y); \
    fma2(acc[1],  w1x, h0.x); fma2(acc[1],  w1y, h0.y); \
    fma2(acc[2],  w2.x, h0.x); fma2(acc[2],  w2.y, h0.y); \
    fma2(acc[3],  w3.x, h0.x); fma2(acc[3],  w3.y, h0.y); \
    fma2(acc[4],  w0x, h1.x); fma2(acc[4],  w0y, h1.y); \
    fma2(acc[5],  w1x, h1.x); fma2(acc[5],  w1y, h1.y); \
    fma2(acc[6],  w2.x, h1.x); fma2(acc[6],  w2.y, h1.y); \
    fma2(acc[7],  w3.x, h1.x); fma2(acc[7],  w3.y, h1.y); \
    fma2(acc[8],  w0x, h2.x); fma2(acc[8],  w0y, h2.y); \
    fma2(acc[9],  w1x, h2.x); fma2(acc[9],  w1y, h2.y); \
    fma2(acc[10], w2.x, h2.x); fma2(acc[10], w2.y, h2.y); \
    fma2(acc[11], w3.x, h2.x); fma2(acc[11], w3.y, h2.y); \
    fma2(acc[12], w0x, h3.x); fma2(acc[12], w0y, h3.y); \
    fma2(acc[13], w1x, h3.x); fma2(acc[13], w1y, h3.y); \
    fma2(acc[14], w2.x, h3.x); fma2(acc[14], w2.y, h3.y); \
    fma2(acc[15], w3.x, h3.x); fma2(acc[15], w3.y, h3.y); }

template <int S0>
static __device__ __forceinline__ void gru_steps(
    float* ws, float* hbuf, float* part,
    float* p0, float* p1, float* p2, float* p3,
    const float* gxp, int tid, int U0,
    float bhr, float bhz, float bhn)
{
    const int g = tid >> 3;
    const int q = tid & 7;
    const float* wp = ws + (g << 2) * 256;

    unsigned long long wa0[16], wa1[16];
#pragma unroll
    for (int s = 0; s < 8; s++) {
        const int kb = (s * 8 + q) * 4;
        ulonglong2 t0 = *(const ulonglong2*)(wp + 0 * 256 + kb);
        ulonglong2 t1 = *(const ulonglong2*)(wp + 1 * 256 + kb);
        wa0[2 * s] = t0.x; wa0[2 * s + 1] = t0.y;
        wa1[2 * s] = t1.x; wa1[2 * s + 1] = t1.y;
    }

    const int gu = tid & 63;
    const int gb = (tid >> 6) & 3;
    const bool is_gate = (tid < 256);
    float hprev = 0.0f;
    float* peer_hb[CLUSTER] = {p0, p1, p2, p3};

    for (int t = 0; t < SEQ; t++) {
        const int cur = t & 1;
        const int nxt = cur ^ 1;

        // gx prefetch for step t (hidden under pre-dot + wait + main dot)
        float gcr = 0.f, gcz = 0.f, gcn = 0.f;
        if (is_gate) {
            const float* gp = gxp + (long)t * G3;
            gcr = gp[0]; gcz = gp[256]; gcn = gp[512];
        }

        const float* hb = hbuf + cur * 4 * HPAD;
        unsigned long long acc[16];
#pragma unroll
        for (int i = 0; i < 16; i++) acc[i] = 0ull;

        // PRE-DOT: own k-slice (locally produced h) — overlaps the barrier
        DOT_S(S0)
        DOT_S(S0 + 1)

        cluster_wait();   // all peers' h(cur) now visible

        // MAIN DOT: remaining 6 slabs (compile-time skip of S0, S0+1)
#pragma unroll
        for (int s = 0; s < 8; s++)
            if (s != S0 && s != S0 + 1) DOT_S(s)

        // Horizontal k-pair sum, store 4 rows per batch as one STS.128
        {
            float* pq = part + q * PBLK + (g << 2);
#pragma unroll
            for (int b = 0; b < 4; b++) {
                float2 f0 = unp2(acc[b * 4 + 0]);
                float2 f1 = unp2(acc[b * 4 + 1]);
                float2 f2 = unp2(acc[b * 4 + 2]);
                float2 f3 = unp2(acc[b * 4 + 3]);
                float4 o;
                o.x = f0.x + f0.y; o.y = f1.x + f1.y;
                o.z = f2.x + f2.y; o.w = f3.x + f3.y;
                *(float4*)(pq + b * 192) = o;
            }
        }
        __syncthreads();

        if (is_gate) {
            float sr = bhr, sz = bhz, sn = bhn;
#pragma unroll
            for (int qq = 0; qq < 8; qq++) {
                const float* pq = part + qq * PBLK + gb * 192;
                sr += pq[gu];
                sz += pq[64 + gu];
                sn += pq[128 + gu];
            }
            float rg = __fdividef(1.0f, 1.0f + __expf(-(gcr + sr)));
            float zg = __fdividef(1.0f, 1.0f + __expf(-(gcz + sz)));
            float na = gcn + rg * sn;
            float ng = 2.0f * __fdividef(1.0f, 1.0f + __expf(-2.0f * na)) - 1.0f;
            float hnew = ng + zg * (hprev - ng);
            hprev = hnew;
            const int off = (nxt * 4 + gb) * HPAD + (U0 + gu);
#pragma unroll
            for (int rr = 0; rr < CLUSTER; rr++)
                peer_hb[rr][off] = hnew;
        }
        cluster_arrive();    // release peers (after DSMEM stores issued)
        __syncthreads();     // publish own h slice locally for next pre-dot
    }
}

__global__ void __launch_bounds__(NTHR, 1) __cluster_dims__(CLUSTER, 1, 1)
gru_rec(const float* __restrict__ Wh, const float* __restrict__ bh,
        const float* __restrict__ Wfc, const float* __restrict__ bfc,
        float* __restrict__ out) {
    extern __shared__ float sm[];
    float* ws   = sm;
    float* hbuf = sm + OFF_HB;
    float* part = sm + OFF_P;

    cg::cluster_group cl = cg::this_cluster();
    const int rank = (int)cl.block_rank();
    const int clid = (int)blockIdx.x / CLUSTER;
    const int tid  = threadIdx.x;
    const int U0   = rank * UB;
    const int B0   = clid * 4;

    for (int e4 = tid; e4 < ROWS * (HID / 4); e4 += NTHR) {
        int r = e4 >> 6;
        int k = (e4 & 63) << 2;
        int grow = (r >> 6) * HID + U0 + (r & 63);
        *(float4*)&ws[r * 256 + k] = *(const float4*)&Wh[(long)grow * HID + k];
    }
    for (int i = tid; i < 2 * 4 * HPAD; i += NTHR)
        hbuf[i] = 0.0f;
    __syncthreads();

    const int gu = tid & 63;
    const float bhr = (tid < 256) ? bh[U0 + gu]       : 0.f;
    const float bhz = (tid < 256) ? bh[256 + U0 + gu] : 0.f;
    const float bhn = (tid < 256) ? bh[512 + U0 + gu] : 0.f;

    float* p0 = (float*)cl.map_shared_rank(hbuf, 0);
    float* p1 = (float*)cl.map_shared_rank(hbuf, 1);
    float* p2 = (float*)cl.map_shared_rank(hbuf, 2);
    float* p3 = (float*)cl.map_shared_rank(hbuf, 3);

    const int gb = (tid >> 6) & 3;
    const float* gxp = g_gx + ((long)(B0 + gb) * SEQ) * G3 + (U0 + gu);

    cl.sync();          // zeroed hbufs visible cluster-wide
    cluster_arrive();   // prime the first in-loop wait

    switch (rank) {
        case 0: gru_steps<0>(ws, hbuf, part, p0, p1, p2, p3, gxp, tid, U0, bhr, bhz, bhn); break;
        case 1: gru_steps<2>(ws, hbuf, part, p0, p1, p2, p3, gxp, tid, U0, bhr, bhz, bhn); break;
        case 2: gru_steps<4>(ws, hbuf, part, p0, p1, p2, p3, gxp, tid, U0, bhr, bhz, bhn); break;
        default: gru_steps<6>(ws, hbuf, part, p0, p1, p2, p3, gxp, tid, U0, bhr, bhz, bhn); break;
    }

    cluster_wait();     // drain final arrive; final h(2048) in hbuf[0]

    if (rank == 0) {
        const int w = tid >> 5, lane = tid & 31;
        if (w < 8) {
            const int bb = w >> 1, o = w & 1;
            const float* hf = hbuf + bb * HPAD;
            float s = 0.f;
            for (int k = lane; k < HID; k += 32)
                s += hf[k] * __ldg(&Wfc[o * HID + k]);
#pragma unroll
            for (int d = 16; d > 0; d >>= 1)
                s += __shfl_xor_sync(0xFFFFFFFFu, s, d);
            if (lane == 0)
                out[(B0 + bb) * 2 + o] = s + bfc[o];
        }
    }
}

// ---------------------------------------------------------------------------
extern "C" void kernel_launch(void* const* d_in, const int* in_sizes, int n_in,
                              void* d_out, int out_size) {
    const float* x   = (const float*)d_in[0];
    const float* Wx  = (const float*)d_in[1];
    const float* bx  = (const float*)d_in[2];
    const float* Wh  = (const float*)d_in[3];
    const float* bh  = (const float*)d_in[4];
    const float* Wfc = (const float*)d_in[5];
    const float* bfc = (const float*)d_in[6];
    float* out = (float*)d_out;

    cudaFuncSetAttribute(gx_gemm, cudaFuncAttributeMaxDynamicSharedMemorySize, GX_SMEM);
    cudaFuncSetAttribute(gru_rec, cudaFuncAttributeMaxDynamicSharedMemorySize, REC_SMEM);

    const int mtiles = (128 * SEQ) / 128;    // 2048
    const int ntiles = G3 / 128;             // 6
    gx_gemm<<<mtiles * ntiles, 256, GX_SMEM>>>(x, Wx, bx);
    gru_rec<<<32 * CLUSTER, NTHR, REC_SMEM>>>(Wh, bh, Wfc, bfc, out);
}